// round 4
// baseline (speedup 1.0000x reference)
#include <cuda_runtime.h>

#define BB 8
#define NN 65536
#define CC 512
#define DD 128
#define ITERS 10

#define TILE_P 128
#define CHUNK  64
#define PSTRIDE 258   // floats per point-pair row: 128 float2 + 2 pad
#define CSTRIDE 68    // floats per k-row of center chunk: 64 + 4 pad

// k_assign smem: points 64*258, centers 128*68, cnorm 512, t1 128
#define SMEM_FLOATS (64*PSTRIDE + 128*CSTRIDE + CC + TILE_P)
#define SMEM_BYTES  (SMEM_FLOATS * 4)

__device__ float g_centers[BB*CC*DD];
__device__ float g_cnorm[BB*CC];
__device__ float g_t1[BB*NN];
__device__ int   g_assign[BB*NN];
__device__ int   g_list[BB*NN];
__device__ int   g_off[BB*CC];
__device__ int   g_cnt[BB*CC];

__device__ __forceinline__ unsigned long long dup2(float x) {
    unsigned long long r;
    asm("mov.b64 %0, {%1, %1};" : "=l"(r) : "f"(x));
    return r;
}
__device__ __forceinline__ void fma2(unsigned long long &d,
                                     unsigned long long a,
                                     unsigned long long b) {
    asm("fma.rn.f32x2 %0, %1, %2, %0;" : "+l"(d) : "l"(a), "l"(b));
}

// LLVM-style vectorized sum of v[k]^2 over k=0..127:
// VF=4, IC=2, fused fma, lanewise combine, faddp horizontal (adjacent pairs).
__device__ __forceinline__ float norm128_llvm(const float* __restrict__ v) {
    float A0=0.f,A1=0.f,A2=0.f,A3=0.f;   // elements 8i + 0..3
    float B0=0.f,B1=0.f,B2=0.f,B3=0.f;   // elements 8i + 4..7
    #pragma unroll
    for (int i = 0; i < 16; i++) {
        const float* p = v + 8*i;
        A0 = __fmaf_rn(p[0], p[0], A0);
        A1 = __fmaf_rn(p[1], p[1], A1);
        A2 = __fmaf_rn(p[2], p[2], A2);
        A3 = __fmaf_rn(p[3], p[3], A3);
        B0 = __fmaf_rn(p[4], p[4], B0);
        B1 = __fmaf_rn(p[5], p[5], B1);
        B2 = __fmaf_rn(p[6], p[6], B2);
        B3 = __fmaf_rn(p[7], p[7], B3);
    }
    float S0 = __fadd_rn(A0, B0);
    float S1 = __fadd_rn(A1, B1);
    float S2 = __fadd_rn(A2, B2);
    float S3 = __fadd_rn(A3, B3);
    return __fadd_rn(__fadd_rn(S0, S1), __fadd_rn(S2, S3));
}

// ---------------------------------------------------------------------------
__global__ void k_init(const float* __restrict__ centersIn) {
    int i = blockIdx.x * blockDim.x + threadIdx.x;
    if (i < BB*CC*DD) g_centers[i] = centersIn[i];
}

// t1[b,n] = ||x||^2 with the XLA:CPU reduce pattern (once; data is constant)
__global__ void k_t1(const float* __restrict__ data) {
    int i = blockIdx.x * blockDim.x + threadIdx.x;
    if (i >= BB*NN) return;
    g_t1[i] = norm128_llvm(data + (size_t)i * DD);
}

// t2[b,c] = ||c||^2 with the same pattern (per iteration)
__global__ void k_prep() {
    int i = blockIdx.x * blockDim.x + threadIdx.x;
    if (i >= BB*CC) return;
    g_cnorm[i] = norm128_llvm(g_centers + (size_t)i * DD);
}

// ---------------------------------------------------------------------------
// Assign: d2 = (t1 - 2*dot) + t2; dot = single ascending-k fused-FMA chain.
// grid = (N/TILE_P, B), block = 256.
__launch_bounds__(256, 2)
__global__ void k_assign(const float* __restrict__ data) {
    extern __shared__ float sm[];
    float* ptsS = sm;                         // [64 pairs][PSTRIDE]
    float* cenS = ptsS + 64*PSTRIDE;          // [128 k][CSTRIDE]
    float* cnS  = cenS + 128*CSTRIDE;         // [512]
    float* t1S  = cnS + CC;                   // [128]

    const int b  = blockIdx.y;
    const int n0 = blockIdx.x * TILE_P;
    const int tid = threadIdx.x;

    for (int i = tid; i < CC; i += 256) cnS[i] = g_cnorm[b*CC + i];
    if (tid < TILE_P) t1S[tid] = g_t1[b*NN + n0 + tid];

    // Load point tile, pair-packed: ptsS[p>>1][2k + (p&1)] = x_p[k]
    const float* dptr = data + ((size_t)b*NN + n0) * DD;
    for (int idx = tid; idx < TILE_P*32; idx += 256) {
        int p = idx & 127;
        int q = idx >> 7;
        float4 v = ((const float4*)(dptr + (size_t)p*DD))[q];
        float* dst = ptsS + (p >> 1)*PSTRIDE + (p & 1);
        int k4 = q * 4;
        dst[(k4+0)*2] = v.x; dst[(k4+1)*2] = v.y;
        dst[(k4+2)*2] = v.z; dst[(k4+3)*2] = v.w;
    }

    const int pg = tid >> 3;   // pairs 2pg,2pg+1 -> points 4pg..4pg+3
    const int cg = tid & 7;    // centers cg*8..cg*8+7 within chunk

    float bv[4]; int bi[4];
    #pragma unroll
    for (int i = 0; i < 4; i++) { bv[i] = 3.4e38f; bi[i] = 0; }

    const float* cbase = g_centers + (size_t)b*CC*DD;

    for (int c0 = 0; c0 < CC; c0 += CHUNK) {
        __syncthreads();
        for (int idx = tid; idx < CHUNK*32; idx += 256) {
            int c = idx & 63;
            int q = idx >> 6;
            float4 v = ((const float4*)(cbase + (size_t)(c0 + c)*DD))[q];
            cenS[(4*q+0)*CSTRIDE + c] = v.x;
            cenS[(4*q+1)*CSTRIDE + c] = v.y;
            cenS[(4*q+2)*CSTRIDE + c] = v.z;
            cenS[(4*q+3)*CSTRIDE + c] = v.w;
        }
        __syncthreads();

        // single sequential 128-FMA chain per (point, center)
        unsigned long long acc[2][8];
        #pragma unroll
        for (int i = 0; i < 2; i++)
            #pragma unroll
            for (int j = 0; j < 8; j++) acc[i][j] = 0ull;

        const float* prow0 = ptsS + (2*pg + 0)*PSTRIDE;
        const float* prow1 = ptsS + (2*pg + 1)*PSTRIDE;

        #pragma unroll 4
        for (int k = 0; k < DD; k++) {
            unsigned long long p0 = *(const unsigned long long*)(prow0 + 2*k);
            unsigned long long p1 = *(const unsigned long long*)(prow1 + 2*k);
            float4 cA = *(const float4*)(cenS + k*CSTRIDE + cg*8);
            float4 cB = *(const float4*)(cenS + k*CSTRIDE + cg*8 + 4);
            unsigned long long cd0 = dup2(cA.x), cd1 = dup2(cA.y);
            unsigned long long cd2 = dup2(cA.z), cd3 = dup2(cA.w);
            unsigned long long cd4 = dup2(cB.x), cd5 = dup2(cB.y);
            unsigned long long cd6 = dup2(cB.z), cd7 = dup2(cB.w);
            fma2(acc[0][0], p0, cd0); fma2(acc[1][0], p1, cd0);
            fma2(acc[0][1], p0, cd1); fma2(acc[1][1], p1, cd1);
            fma2(acc[0][2], p0, cd2); fma2(acc[1][2], p1, cd2);
            fma2(acc[0][3], p0, cd3); fma2(acc[1][3], p1, cd3);
            fma2(acc[0][4], p0, cd4); fma2(acc[1][4], p1, cd4);
            fma2(acc[0][5], p0, cd5); fma2(acc[1][5], p1, cd5);
            fma2(acc[0][6], p0, cd6); fma2(acc[1][6], p1, cd6);
            fma2(acc[0][7], p0, cd7); fma2(acc[1][7], p1, cd7);
        }

        // d2 = (t1 - 2*dot) + cnorm, rn ops in reference association
        float t1a = t1S[4*pg + 0], t1b = t1S[4*pg + 1];
        float t1c = t1S[4*pg + 2], t1d = t1S[4*pg + 3];
        #pragma unroll
        for (int j = 0; j < 8; j++) {
            int cidx = c0 + cg*8 + j;
            float cn = cnS[cidx];
            float2 f0 = *(float2*)&acc[0][j];
            float2 f1 = *(float2*)&acc[1][j];
            float s0 = __fadd_rn(__fsub_rn(t1a, __fmul_rn(2.0f, f0.x)), cn);
            float s1 = __fadd_rn(__fsub_rn(t1b, __fmul_rn(2.0f, f0.y)), cn);
            float s2 = __fadd_rn(__fsub_rn(t1c, __fmul_rn(2.0f, f1.x)), cn);
            float s3 = __fadd_rn(__fsub_rn(t1d, __fmul_rn(2.0f, f1.y)), cn);
            if (s0 < bv[0]) { bv[0] = s0; bi[0] = cidx; }
            if (s1 < bv[1]) { bv[1] = s1; bi[1] = cidx; }
            if (s2 < bv[2]) { bv[2] = s2; bi[2] = cidx; }
            if (s3 < bv[3]) { bv[3] = s3; bi[3] = cidx; }
        }
    }

    // argmin across the 8 cg-lanes per point (tie -> lowest index)
    #pragma unroll
    for (int i = 0; i < 4; i++) {
        float v = bv[i]; int ix = bi[i];
        #pragma unroll
        for (int off = 4; off; off >>= 1) {
            float ov = __shfl_xor_sync(0xffffffffu, v, off);
            int   oi = __shfl_xor_sync(0xffffffffu, ix, off);
            if (ov < v || (ov == v && oi < ix)) { v = ov; ix = oi; }
        }
        if (cg == 0) g_assign[b*NN + n0 + 4*pg + i] = ix;
    }
}

// ---------------------------------------------------------------------------
// Stable counting sort of points by cluster (ascending n within cluster).
__global__ void k_sort() {
    __shared__ int hist[CC];
    __shared__ int cursor[CC];
    __shared__ int wt[CC];
    extern __shared__ int W[];   // [32 warps][CC]

    int b = blockIdx.x, tid = threadIdx.x;
    int w = tid >> 5, lane = tid & 31;

    for (int i = tid; i < CC; i += 1024) hist[i] = 0;
    __syncthreads();
    for (int n = tid; n < NN; n += 1024)
        atomicAdd(&hist[g_assign[b*NN + n]], 1);
    __syncthreads();
    if (tid == 0) {
        int run = 0;
        for (int c = 0; c < CC; c++) {
            cursor[c] = run;
            g_off[b*CC + c] = run;
            int h = hist[c];
            g_cnt[b*CC + c] = h;
            run += h;
        }
    }
    __syncthreads();

    for (int wave = 0; wave < NN/1024; wave++) {
        for (int i = tid; i < 32*CC; i += 1024) W[i] = 0;
        __syncthreads();
        int n = wave*1024 + tid;
        int a = g_assign[b*NN + n];
        unsigned mask = __match_any_sync(0xffffffffu, a);
        int rank = __popc(mask & ((1u << lane) - 1u));
        if (rank == 0) W[w*CC + a] = __popc(mask);
        __syncthreads();
        if (tid < CC) {
            int s = 0;
            for (int ww = 0; ww < 32; ww++) {
                int t = W[ww*CC + tid];
                W[ww*CC + tid] = s;
                s += t;
            }
            wt[tid] = s;
        }
        __syncthreads();
        int pos = cursor[a] + W[w*CC + a] + rank;
        g_list[b*NN + pos] = n;
        __syncthreads();
        if (tid < CC) cursor[tid] += wt[tid];
        __syncthreads();
    }
}

// ---------------------------------------------------------------------------
// New centers: sequential ascending-n fp32 adds per (b,c,d), then rn divide.
__global__ void k_update(const float* __restrict__ data) {
    __shared__ int listS[128];
    int c = blockIdx.x, b = blockIdx.y, d = threadIdx.x;
    int off = g_off[b*CC + c];
    int cnt = g_cnt[b*CC + c];
    float acc = 0.f;
    for (int base = 0; base < cnt; base += 128) {
        __syncthreads();
        int m = min(128, cnt - base);
        if (d < m) listS[d] = g_list[b*NN + off + base + d];
        __syncthreads();
        for (int j = 0; j < m; j++) {
            int n = listS[j];
            acc = __fadd_rn(acc, __ldg(&data[((size_t)b*NN + n)*DD + d]));
        }
    }
    if (cnt > 0)
        g_centers[(size_t)(b*CC + c)*DD + d] = __fdiv_rn(acc, __int2float_rn(cnt));
}

// d_out = [centers (B*C*D) | (float)assign broadcast over D (B*N*D)]
__global__ void k_output(float* __restrict__ out) {
    size_t i = (size_t)blockIdx.x * blockDim.x + threadIdx.x;
    const size_t nc = (size_t)BB*CC*DD;
    const size_t total = nc + (size_t)BB*NN*DD;
    if (i >= total) return;
    if (i < nc) out[i] = g_centers[i];
    else {
        size_t j = i - nc;
        out[i] = (float)g_assign[j >> 7];
    }
}

// ---------------------------------------------------------------------------
extern "C" void kernel_launch(void* const* d_in, const int* in_sizes, int n_in,
                              void* d_out, int out_size) {
    const float* data      = (const float*)d_in[0];
    const float* centersIn = (const float*)d_in[1];
    float* out = (float*)d_out;

    cudaFuncSetAttribute(k_assign, cudaFuncAttributeMaxDynamicSharedMemorySize,
                         SMEM_BYTES);
    cudaFuncSetAttribute(k_sort, cudaFuncAttributeMaxDynamicSharedMemorySize,
                         32*CC*(int)sizeof(int));

    k_init<<<(BB*CC*DD + 255)/256, 256>>>(centersIn);
    k_t1<<<(BB*NN + 255)/256, 256>>>(data);
    for (int it = 0; it < ITERS; it++) {
        k_prep<<<(BB*CC + 255)/256, 256>>>();
        k_assign<<<dim3(NN/TILE_P, BB), 256, SMEM_BYTES>>>(data);
        k_sort<<<BB, 1024, 32*CC*(int)sizeof(int)>>>();
        k_update<<<dim3(CC, BB), 128>>>(data);
    }
    const size_t total = (size_t)BB*CC*DD + (size_t)BB*NN*DD;
    k_output<<<(unsigned)((total + 255)/256), 256>>>(out);
}

// round 5
// speedup vs baseline: 1.2854x; 1.2854x over previous
#include <cuda_runtime.h>

#define BB 8
#define NN 65536
#define CC 512
#define DD 128
#define ITERS 10

#define TILE_P 128
#define CHUNK  32
#define QSTRIDE 516   // words per point-quad row: 4*128 + 4 (bank-staggered)
#define CROW    64    // words per k-row of duplicated center chunk (32 c * 2)

// k_assign smem: points 32*516, centers 128*64, cnorm 512
#define SMEM_FLOATS (32*QSTRIDE + 128*CROW + CC)
#define SMEM_BYTES  (SMEM_FLOATS * 4)

__device__ float g_centers[BB*CC*DD];
__device__ float g_cTd[BB*DD*CC*2];     // [b][k][2c] duplicated k-major centers
__device__ float g_cnorm[BB*CC];
__device__ float g_t1[BB*NN];
__device__ int   g_assign[BB*NN];
__device__ int   g_list[BB*NN];
__device__ int   g_off[BB*CC];
__device__ int   g_cnt[BB*CC];

__device__ __forceinline__ void fma2(unsigned long long &d,
                                     unsigned long long a,
                                     unsigned long long b) {
    asm("fma.rn.f32x2 %0, %1, %2, %0;" : "+l"(d) : "l"(a), "l"(b));
}

// LLVM-style vectorized sum of v[k]^2: VF=4, IC=2, fma, lanewise, faddp.
__device__ __forceinline__ float norm128_llvm(const float* __restrict__ v) {
    float A0=0.f,A1=0.f,A2=0.f,A3=0.f;
    float B0=0.f,B1=0.f,B2=0.f,B3=0.f;
    #pragma unroll
    for (int i = 0; i < 16; i++) {
        const float* p = v + 8*i;
        A0 = __fmaf_rn(p[0], p[0], A0);
        A1 = __fmaf_rn(p[1], p[1], A1);
        A2 = __fmaf_rn(p[2], p[2], A2);
        A3 = __fmaf_rn(p[3], p[3], A3);
        B0 = __fmaf_rn(p[4], p[4], B0);
        B1 = __fmaf_rn(p[5], p[5], B1);
        B2 = __fmaf_rn(p[6], p[6], B2);
        B3 = __fmaf_rn(p[7], p[7], B3);
    }
    float S0 = __fadd_rn(A0, B0);
    float S1 = __fadd_rn(A1, B1);
    float S2 = __fadd_rn(A2, B2);
    float S3 = __fadd_rn(A3, B3);
    return __fadd_rn(__fadd_rn(S0, S1), __fadd_rn(S2, S3));
}

// ---------------------------------------------------------------------------
__global__ void k_init(const float* __restrict__ centersIn) {
    int i = blockIdx.x * blockDim.x + threadIdx.x;
    if (i < BB*CC*DD) g_centers[i] = centersIn[i];
}

__global__ void k_t1(const float* __restrict__ data) {
    int i = blockIdx.x * blockDim.x + threadIdx.x;
    if (i >= BB*NN) return;
    g_t1[i] = norm128_llvm(data + (size_t)i * DD);
}

__global__ void k_prep() {
    int i = blockIdx.x * blockDim.x + threadIdx.x;
    if (i >= BB*CC) return;
    g_cnorm[i] = norm128_llvm(g_centers + (size_t)i * DD);
}

// transpose + duplicate centers into k-major scratch: g_cTd[b][k][2c+{0,1}]
__global__ void k_transpose() {
    int i = blockIdx.x * blockDim.x + threadIdx.x;   // (b*DD + k)*CC + c
    if (i >= BB*DD*CC) return;
    int c = i % CC;
    int bk = i / CC;
    int k = bk % DD;
    int b = bk / DD;
    float v = g_centers[((size_t)b*CC + c)*DD + k];
    float2* dst = (float2*)(g_cTd + (size_t)i*2);
    *dst = make_float2(v, v);
}

// ---------------------------------------------------------------------------
// Assign: d2 = (t1 - 2*dot) + t2; dot = single ascending-k fused-FMA chain.
// grid = (N/TILE_P, B), block = 128. Each thread: 8 points x 4 centers.
__launch_bounds__(128, 2)
__global__ void k_assign(const float* __restrict__ data) {
    extern __shared__ float sm[];
    float* ptsS = sm;                   // [32 quads][QSTRIDE]: quad q, word 4k+j
    float* cenS = ptsS + 32*QSTRIDE;    // [128 k][CROW] duplicated center pairs
    float* cnS  = cenS + 128*CROW;      // [512]

    const int b  = blockIdx.y;
    const int n0 = blockIdx.x * TILE_P;
    const int tid = threadIdx.x;

    for (int i = tid; i < CC; i += 128) cnS[i] = g_cnorm[b*CC + i];

    // Load point tile quad-packed: ptsS[p>>2][4k + (p&3)] = x_p[k]
    const float* dptr = data + ((size_t)b*NN + n0) * DD;
    for (int idx = tid; idx < TILE_P*32; idx += 128) {
        int p = idx & 127;
        int q = idx >> 7;
        float4 v = ((const float4*)(dptr + (size_t)p*DD))[q];
        float* dst = ptsS + (p >> 2)*QSTRIDE + (p & 3);
        int k4 = q * 4;
        dst[(k4+0)*4] = v.x; dst[(k4+1)*4] = v.y;
        dst[(k4+2)*4] = v.z; dst[(k4+3)*4] = v.w;
    }

    const int pg = tid >> 3;   // 0..15 : points 8pg..8pg+7 (quads 2pg, 2pg+1)
    const int cg = tid & 7;    // 0..7  : centers {2cg,2cg+1,16+2cg,16+2cg+1}

    // per-point t1 in registers (iteration-invariant)
    float t1r[8];
    #pragma unroll
    for (int i = 0; i < 8; i++) t1r[i] = g_t1[b*NN + n0 + 8*pg + i];

    float bv[8]; int bi[8];
    #pragma unroll
    for (int i = 0; i < 8; i++) { bv[i] = 3.4e38f; bi[i] = 0; }

    const float* ctd = g_cTd + (size_t)b*DD*CC*2;

    const float* q0p = ptsS + (2*pg)*QSTRIDE;
    const float* q1p = q0p + QSTRIDE;

    for (int c0 = 0; c0 < CC; c0 += CHUNK) {
        __syncthreads();
        // fill duplicated center chunk: cenS[k][w] = g_cTd[b][k][2*c0 + w]
        #pragma unroll
        for (int it = 0; it < 16; it++) {
            int idx = it*128 + tid;
            int k  = idx >> 4;
            int w4 = (idx & 15) << 2;
            *(float4*)(cenS + k*CROW + w4) =
                *(const float4*)(ctd + (size_t)k*CC*2 + c0*2 + w4);
        }
        __syncthreads();

        unsigned long long acc[4][4];  // [point pair e][center j]
        #pragma unroll
        for (int e = 0; e < 4; e++)
            #pragma unroll
            for (int j = 0; j < 4; j++) acc[e][j] = 0ull;

        const float* cen0 = cenS + 4*cg;        // centers 2cg, 2cg+1 (dup)
        const float* cen1 = cenS + 32 + 4*cg;   // centers 16+2cg, +1 (dup)

        #pragma unroll 4
        for (int k = 0; k < DD; k++) {
            ulonglong2 Q0 = *(const ulonglong2*)(q0p + 4*k);  // pts 8pg..+3
            ulonglong2 Q1 = *(const ulonglong2*)(q1p + 4*k);  // pts 8pg+4..+7
            ulonglong2 CA = *(const ulonglong2*)(cen0 + k*CROW);
            ulonglong2 CB = *(const ulonglong2*)(cen1 + k*CROW);
            fma2(acc[0][0], Q0.x, CA.x); fma2(acc[1][0], Q0.y, CA.x);
            fma2(acc[2][0], Q1.x, CA.x); fma2(acc[3][0], Q1.y, CA.x);
            fma2(acc[0][1], Q0.x, CA.y); fma2(acc[1][1], Q0.y, CA.y);
            fma2(acc[2][1], Q1.x, CA.y); fma2(acc[3][1], Q1.y, CA.y);
            fma2(acc[0][2], Q0.x, CB.x); fma2(acc[1][2], Q0.y, CB.x);
            fma2(acc[2][2], Q1.x, CB.x); fma2(acc[3][2], Q1.y, CB.x);
            fma2(acc[0][3], Q0.x, CB.y); fma2(acc[1][3], Q0.y, CB.y);
            fma2(acc[2][3], Q1.x, CB.y); fma2(acc[3][3], Q1.y, CB.y);
        }

        // d2 = (t1 - 2*dot) + cnorm, rn ops in reference association
        #pragma unroll
        for (int j = 0; j < 4; j++) {
            int cidx = c0 + ((j < 2) ? (2*cg + j) : (16 + 2*cg + (j - 2)));
            float cn = cnS[cidx];
            #pragma unroll
            for (int e = 0; e < 4; e++) {
                float2 f = *(float2*)&acc[e][j];
                float slo = __fadd_rn(__fsub_rn(t1r[2*e],   __fmul_rn(2.0f, f.x)), cn);
                float shi = __fadd_rn(__fsub_rn(t1r[2*e+1], __fmul_rn(2.0f, f.y)), cn);
                if (slo < bv[2*e])   { bv[2*e]   = slo; bi[2*e]   = cidx; }
                if (shi < bv[2*e+1]) { bv[2*e+1] = shi; bi[2*e+1] = cidx; }
            }
        }
    }

    // argmin across the 8 cg-lanes per point (tie -> lowest index)
    #pragma unroll
    for (int i = 0; i < 8; i++) {
        float v = bv[i]; int ix = bi[i];
        #pragma unroll
        for (int off = 4; off; off >>= 1) {
            float ov = __shfl_xor_sync(0xffffffffu, v, off);
            int   oi = __shfl_xor_sync(0xffffffffu, ix, off);
            if (ov < v || (ov == v && oi < ix)) { v = ov; ix = oi; }
        }
        if (cg == 0) g_assign[b*NN + n0 + 8*pg + i] = ix;
    }
}

// ---------------------------------------------------------------------------
// Stable counting sort of points by cluster (ascending n within cluster).
__global__ void k_sort() {
    __shared__ int hist[CC];
    __shared__ int cursor[CC];
    __shared__ int wt[CC];
    extern __shared__ int W[];   // [32 warps][CC]

    int b = blockIdx.x, tid = threadIdx.x;
    int w = tid >> 5, lane = tid & 31;

    for (int i = tid; i < CC; i += 1024) hist[i] = 0;
    __syncthreads();
    for (int n = tid; n < NN; n += 1024)
        atomicAdd(&hist[g_assign[b*NN + n]], 1);
    __syncthreads();
    if (tid == 0) {
        int run = 0;
        for (int c = 0; c < CC; c++) {
            cursor[c] = run;
            g_off[b*CC + c] = run;
            int h = hist[c];
            g_cnt[b*CC + c] = h;
            run += h;
        }
    }
    __syncthreads();

    for (int wave = 0; wave < NN/1024; wave++) {
        for (int i = tid; i < 32*CC; i += 1024) W[i] = 0;
        __syncthreads();
        int n = wave*1024 + tid;
        int a = g_assign[b*NN + n];
        unsigned mask = __match_any_sync(0xffffffffu, a);
        int rank = __popc(mask & ((1u << lane) - 1u));
        if (rank == 0) W[w*CC + a] = __popc(mask);
        __syncthreads();
        if (tid < CC) {
            int s = 0;
            for (int ww = 0; ww < 32; ww++) {
                int t = W[ww*CC + tid];
                W[ww*CC + tid] = s;
                s += t;
            }
            wt[tid] = s;
        }
        __syncthreads();
        int pos = cursor[a] + W[w*CC + a] + rank;
        g_list[b*NN + pos] = n;
        __syncthreads();
        if (tid < CC) cursor[tid] += wt[tid];
        __syncthreads();
    }
}

// ---------------------------------------------------------------------------
// New centers: sequential ascending-n fp32 adds per (b,c,d), then rn divide.
__global__ void k_update(const float* __restrict__ data) {
    __shared__ int listS[128];
    int c = blockIdx.x, b = blockIdx.y, d = threadIdx.x;
    int off = g_off[b*CC + c];
    int cnt = g_cnt[b*CC + c];
    float acc = 0.f;
    for (int base = 0; base < cnt; base += 128) {
        __syncthreads();
        int m = min(128, cnt - base);
        if (d < m) listS[d] = g_list[b*NN + off + base + d];
        __syncthreads();
        for (int j = 0; j < m; j++) {
            int n = listS[j];
            acc = __fadd_rn(acc, __ldg(&data[((size_t)b*NN + n)*DD + d]));
        }
    }
    if (cnt > 0)
        g_centers[(size_t)(b*CC + c)*DD + d] = __fdiv_rn(acc, __int2float_rn(cnt));
}

// d_out = [centers (B*C*D) | (float)assign broadcast over D (B*N*D)]
__global__ void k_output(float* __restrict__ out) {
    size_t i = (size_t)blockIdx.x * blockDim.x + threadIdx.x;
    const size_t nc = (size_t)BB*CC*DD;
    const size_t total = nc + (size_t)BB*NN*DD;
    if (i >= total) return;
    if (i < nc) out[i] = g_centers[i];
    else {
        size_t j = i - nc;
        out[i] = (float)g_assign[j >> 7];
    }
}

// ---------------------------------------------------------------------------
extern "C" void kernel_launch(void* const* d_in, const int* in_sizes, int n_in,
                              void* d_out, int out_size) {
    const float* data      = (const float*)d_in[0];
    const float* centersIn = (const float*)d_in[1];
    float* out = (float*)d_out;

    cudaFuncSetAttribute(k_assign, cudaFuncAttributeMaxDynamicSharedMemorySize,
                         SMEM_BYTES);
    cudaFuncSetAttribute(k_sort, cudaFuncAttributeMaxDynamicSharedMemorySize,
                         32*CC*(int)sizeof(int));

    k_init<<<(BB*CC*DD + 255)/256, 256>>>(centersIn);
    k_t1<<<(BB*NN + 255)/256, 256>>>(data);
    for (int it = 0; it < ITERS; it++) {
        k_prep<<<(BB*CC + 255)/256, 256>>>();
        k_transpose<<<(BB*DD*CC + 255)/256, 256>>>();
        k_assign<<<dim3(NN/TILE_P, BB), 128, SMEM_BYTES>>>(data);
        k_sort<<<BB, 1024, 32*CC*(int)sizeof(int)>>>();
        k_update<<<dim3(CC, BB), 128>>>(data);
    }
    const size_t total = (size_t)BB*CC*DD + (size_t)BB*NN*DD;
    k_output<<<(unsigned)((total + 255)/256), 256>>>(out);
}